// round 3
// baseline (speedup 1.0000x reference)
#include <cuda_runtime.h>
#include <cuda_bf16.h>
#include <cstddef>

// NGCF conv: out = leaky(agg@W1+b1) + leaky((agg*feat)@W2+b2)
// where agg = scatter_add(edge_vals * feat[edge_col], edge_row)
//
// N=100000 nodes, E=1600000 edges, D_IN=D_OUT=64, all fp32.

#define N_NODES 100000
#define N_EDGES 1600000
#define D       64

// Scratch for the aggregated features (allocation-free rule: device global).
__device__ __align__(256) float g_agg[(size_t)N_NODES * D];

// ---------------------------------------------------------------------------
// Kernel 1: zero the aggregation buffer (graph replays re-run this each call).
// Grid-stride float4 writes, 148*4 CTAs -> ~1 wave at occ 8.
// ---------------------------------------------------------------------------
__global__ __launch_bounds__(256) void zero_agg_kernel() {
    const int n4     = (N_NODES * D) / 4;
    const int stride = gridDim.x * blockDim.x;
    float4* p = reinterpret_cast<float4*>(g_agg);
    for (int i = blockIdx.x * blockDim.x + threadIdx.x; i < n4; i += stride) {
        p[i] = make_float4(0.f, 0.f, 0.f, 0.f);
    }
}

// ---------------------------------------------------------------------------
// Kernel 2: edge scatter.  8 lanes per edge; each lane gathers 2 float4 from
// feat[col] (independent LDG.128s -> MLP=2), scales by edge_val, then issues
// 2x red.global.add.v4.f32 into g_agg[row].
// node_feat (25.6MB) + g_agg (25.6MB) stay L2-resident -> L2/REDG bound.
// v4 RED = 4x fewer L2 atomic ops than scalar atomicAdd.
// ---------------------------------------------------------------------------
__global__ __launch_bounds__(256) void scatter_kernel(
    const int*   __restrict__ erow,
    const int*   __restrict__ ecol,
    const float* __restrict__ evals,
    const float* __restrict__ feat)
{
    int tid = blockIdx.x * blockDim.x + threadIdx.x;
    int e   = tid >> 3;          // 8 lanes per edge
    if (e >= N_EDGES) return;
    int sub = tid & 7;           // lane handles float4 slots {sub, sub+8}

    int   row = __ldg(erow + e);   // broadcast within the 8-lane group
    int   col = __ldg(ecol + e);
    float v   = __ldg(evals + e);

    const float4* src = reinterpret_cast<const float4*>(feat + (size_t)col * D);
    // Two independent gathers in flight before any RED (MLP=2).
    float4 f0 = __ldg(src + sub);
    float4 f1 = __ldg(src + sub + 8);
    f0.x *= v; f0.y *= v; f0.z *= v; f0.w *= v;
    f1.x *= v; f1.y *= v; f1.z *= v; f1.w *= v;

    float* dst = g_agg + (size_t)row * D;
    asm volatile("red.global.add.v4.f32 [%0], {%1, %2, %3, %4};"
                 :: "l"(dst + sub * 4),
                    "f"(f0.x), "f"(f0.y), "f"(f0.z), "f"(f0.w)
                 : "memory");
    asm volatile("red.global.add.v4.f32 [%0], {%1, %2, %3, %4};"
                 :: "l"(dst + (sub + 8) * 4),
                    "f"(f1.x), "f"(f1.y), "f"(f1.z), "f"(f1.w)
                 : "memory");
}

// ---------------------------------------------------------------------------
// Kernel 3: fused dual-GEMM epilogue.
//   part1 = leaky(agg @ W1 + b1)
//   part2 = leaky((agg * feat) @ W2 + b2)
//   out   = part1 + part2
// Tile: 32 nodes x 64 outputs per 256-thread block.  W1/W2 (32KB) + A/AF
// tiles (16KB) = 48KB static smem.  Each thread: 2 nodes x 4 cols x 2 GEMMs
// = 16 FMA per k-step.
// ---------------------------------------------------------------------------
__global__ __launch_bounds__(256) void fused_gemm_kernel(
    const float* __restrict__ feat,
    const float* __restrict__ W1,
    const float* __restrict__ b1,
    const float* __restrict__ W2,
    const float* __restrict__ b2,
    float*       __restrict__ out)
{
    __shared__ float W1s[D * D];   // 16 KB  [k][j]
    __shared__ float W2s[D * D];   // 16 KB  [k][j]
    __shared__ float As [32 * D];  //  8 KB  [m][k]  agg tile
    __shared__ float AFs[32 * D];  //  8 KB  [m][k]  agg*feat tile

    const int tid  = threadIdx.x;
    const int base = blockIdx.x * 32;

    // Load weights (row-major [D_IN][D_OUT] == [k][j], exactly what we want)
    #pragma unroll
    for (int i = tid; i < D * D; i += 256) {
        W1s[i] = W1[i];
        W2s[i] = W2[i];
    }

    // Load activation tiles: 32 nodes x 64 feats, coalesced
    #pragma unroll
    for (int i = tid; i < 32 * D; i += 256) {
        int m    = i >> 6;
        int k    = i & 63;
        int node = base + m;
        float a = 0.f, f = 0.f;
        if (node < N_NODES) {
            size_t off = (size_t)node * D + k;
            a = g_agg[off];
            f = feat[off];
        }
        As[i]  = a;
        AFs[i] = a * f;
    }
    __syncthreads();

    const int tx = tid & 15;       // 16 col-groups
    const int ty = tid >> 4;       // 16 row-groups
    const int j0 = tx * 4;         // 4 output columns per thread
    const int m0 = ty * 2;         // 2 nodes per thread

    float acc1[2][4] = {{0.f,0.f,0.f,0.f},{0.f,0.f,0.f,0.f}};
    float acc2[2][4] = {{0.f,0.f,0.f,0.f},{0.f,0.f,0.f,0.f}};

    #pragma unroll 8
    for (int k = 0; k < D; k++) {
        float a0 = As [ m0      * D + k];
        float a1 = As [(m0 + 1) * D + k];
        float f0 = AFs[ m0      * D + k];
        float f1 = AFs[(m0 + 1) * D + k];
        float4 w1 = *reinterpret_cast<const float4*>(&W1s[k * D + j0]);
        float4 w2 = *reinterpret_cast<const float4*>(&W2s[k * D + j0]);

        acc1[0][0] += a0 * w1.x; acc1[0][1] += a0 * w1.y;
        acc1[0][2] += a0 * w1.z; acc1[0][3] += a0 * w1.w;
        acc1[1][0] += a1 * w1.x; acc1[1][1] += a1 * w1.y;
        acc1[1][2] += a1 * w1.z; acc1[1][3] += a1 * w1.w;

        acc2[0][0] += f0 * w2.x; acc2[0][1] += f0 * w2.y;
        acc2[0][2] += f0 * w2.z; acc2[0][3] += f0 * w2.w;
        acc2[1][0] += f1 * w2.x; acc2[1][1] += f1 * w2.y;
        acc2[1][2] += f1 * w2.z; acc2[1][3] += f1 * w2.w;
    }

    // Bias (tiny, L1/L2 cached)
    float4 bb1 = *reinterpret_cast<const float4*>(&b1[j0]);
    float4 bb2 = *reinterpret_cast<const float4*>(&b2[j0]);
    float bias1[4] = {bb1.x, bb1.y, bb1.z, bb1.w};
    float bias2[4] = {bb2.x, bb2.y, bb2.z, bb2.w};

    #pragma unroll
    for (int mi = 0; mi < 2; mi++) {
        int node = base + m0 + mi;
        if (node >= N_NODES) continue;
        float4 r;
        float* rp = &r.x;
        #pragma unroll
        for (int jj = 0; jj < 4; jj++) {
            float x1 = acc1[mi][jj] + bias1[jj];
            float x2 = acc2[mi][jj] + bias2[jj];
            x1 = (x1 >= 0.f) ? x1 : 0.2f * x1;
            x2 = (x2 >= 0.f) ? x2 : 0.2f * x2;
            rp[jj] = x1 + x2;
        }
        *reinterpret_cast<float4*>(out + (size_t)node * D + j0) = r;
    }
}

// ---------------------------------------------------------------------------
// Launch
// ---------------------------------------------------------------------------
extern "C" void kernel_launch(void* const* d_in, const int* in_sizes, int n_in,
                              void* d_out, int out_size)
{
    const int*   erow  = (const int*)  d_in[0];
    const int*   ecol  = (const int*)  d_in[1];
    const float* evals = (const float*)d_in[2];
    const float* feat  = (const float*)d_in[3];
    const float* W1    = (const float*)d_in[4];
    const float* b1    = (const float*)d_in[5];
    const float* W2    = (const float*)d_in[6];
    const float* b2    = (const float*)d_in[7];
    float*       out   = (float*)d_out;

    // 1) zero agg scratch
    zero_agg_kernel<<<148 * 4, 256>>>();

    // 2) edge scatter (8 lanes per edge, 2 float4 each)
    {
        long long threads = (long long)N_EDGES * 8;
        int grid = (int)((threads + 255) / 256);
        scatter_kernel<<<grid, 256>>>(erow, ecol, evals, feat);
    }
    // 3) fused dual-GEMM epilogue
    {
        int grid = (N_NODES + 31) / 32;
        fused_gemm_kernel<<<grid, 256>>>(feat, W1, b1, W2, b2, out);
    }
}